// round 2
// baseline (speedup 1.0000x reference)
#include <cuda_runtime.h>
#include <cstddef>

// out[b,i,j,e] = sum_d (src[b,j,d]-src[b,i,d])*W[e,d] + bias[e]
//             = Y[b,j,e] - Y[b,i,e] + bias[e],  Y = src @ W^T
//
// One block per batch b: GEMM Y[b] (22x128) in SMEM, then stream pairwise
// expansion (22*22*128 floats = 248KB per block) with streaming stores.

#define JDIM 22
#define DDIM 128
#define KCHUNK 32
#define WPAD 33            // odd stride -> conflict-free column reads
#define NTHREADS 256

__global__ __launch_bounds__(NTHREADS, 5)
void spatial_edge_fused(const float* __restrict__ src,
                        const float* __restrict__ W,
                        const float* __restrict__ bias,
                        float* __restrict__ out)
{
    __shared__ float s_src[JDIM * DDIM];     // 22*128 = 2816 floats
    __shared__ float s_W[DDIM * WPAD];       // 128x32 chunk, pad-33
    __shared__ float s_Y[JDIM * DDIM];
    __shared__ float s_b[DDIM];

    const int b   = blockIdx.x;
    const int tid = threadIdx.x;
    const int tx  = tid & 31;   // lane
    const int ty  = tid >> 5;   // warp 0..7

    const float* srcb = src + (size_t)b * (JDIM * DDIM);

    // ---- load src[b] and bias ----
    for (int i = tid; i < JDIM * DDIM; i += NTHREADS) s_src[i] = srcb[i];
    if (tid < DDIM) s_b[tid] = __ldg(&bias[tid]);

    // Each thread owns 16 elements of each W chunk: rows (tid>>4 + 16*q), cols (tid&15)*2..+1
    // Simpler: thread strides the 4096-element chunk by NTHREADS -> 16 elems.
    float wreg[16];
    // Prefetch chunk 0
    #pragma unroll
    for (int q = 0; q < 16; q++) {
        const int i  = tid + q * NTHREADS;      // 0..4095
        const int e  = i >> 5;
        const int dd = i & 31;
        wreg[q] = __ldg(&W[e * DDIM + 0 + dd]);
    }

    // Thread computes rows {ty, ty+8, ty+16} x cols {tx, tx+32, tx+64, tx+96}
    const int row0 = ty;
    const int row1 = ty + 8;
    const bool has2 = (ty < 6);
    const int row2 = has2 ? (ty + 16) : ty;   // clamp to stay in-bounds

    float acc[3][4];
    #pragma unroll
    for (int r = 0; r < 3; r++)
        #pragma unroll
        for (int k = 0; k < 4; k++) acc[r][k] = 0.0f;

    // ---- GEMM: Y = src @ W^T, K in chunks of 32, W double-staged via registers ----
    for (int c = 0; c < DDIM / KCHUNK; c++) {
        __syncthreads();   // prior chunk's reads done (also covers src/bias on c=0)
        // stage prefetched chunk into smem
        #pragma unroll
        for (int q = 0; q < 16; q++) {
            const int i  = tid + q * NTHREADS;
            const int e  = i >> 5;
            const int dd = i & 31;
            s_W[e * WPAD + dd] = wreg[q];
        }
        __syncthreads();

        // prefetch next chunk while computing this one
        if (c + 1 < DDIM / KCHUNK) {
            const int d0n = (c + 1) * KCHUNK;
            #pragma unroll
            for (int q = 0; q < 16; q++) {
                const int i  = tid + q * NTHREADS;
                const int e  = i >> 5;
                const int dd = i & 31;
                wreg[q] = __ldg(&W[e * DDIM + d0n + dd]);
            }
        }

        const int d0 = c * KCHUNK;
        #pragma unroll 4
        for (int dd = 0; dd < KCHUNK; dd++) {
            // cols tx+32k: bank = (tx + dd) mod 32 across lanes -> conflict-free
            const float w0 = s_W[(tx      ) * WPAD + dd];
            const float w1 = s_W[(tx + 32 ) * WPAD + dd];
            const float w2 = s_W[(tx + 64 ) * WPAD + dd];
            const float w3 = s_W[(tx + 96 ) * WPAD + dd];
            const int d = d0 + dd;
            const float s0 = s_src[row0 * DDIM + d];   // broadcast within warp
            const float s1 = s_src[row1 * DDIM + d];
            const float s2 = s_src[row2 * DDIM + d];
            acc[0][0] += s0 * w0; acc[0][1] += s0 * w1;
            acc[0][2] += s0 * w2; acc[0][3] += s0 * w3;
            acc[1][0] += s1 * w0; acc[1][1] += s1 * w1;
            acc[1][2] += s1 * w2; acc[1][3] += s1 * w3;
            acc[2][0] += s2 * w0; acc[2][1] += s2 * w1;
            acc[2][2] += s2 * w2; acc[2][3] += s2 * w3;
        }
    }

    // ---- write Y to shared ----
    __syncthreads();
    #pragma unroll
    for (int k = 0; k < 4; k++) {
        s_Y[row0 * DDIM + tx + 32 * k] = acc[0][k];
        s_Y[row1 * DDIM + tx + 32 * k] = acc[1][k];
    }
    if (has2) {
        #pragma unroll
        for (int k = 0; k < 4; k++)
            s_Y[row2 * DDIM + tx + 32 * k] = acc[2][k];
    }
    __syncthreads();

    // ---- expansion: out[b,i,j,:] = Y[j] - Y[i] + bias, float4 streaming stores ----
    const float4* y4 = reinterpret_cast<const float4*>(s_Y);
    const float4* b4 = reinterpret_cast<const float4*>(s_b);
    float4* outb4 = reinterpret_cast<float4*>(out + (size_t)b * (JDIM * JDIM * DDIM));

    const int total4 = JDIM * JDIM * (DDIM / 4);   // 15488
    for (int idx = tid; idx < total4; idx += NTHREADS) {
        const int e4 = idx & 31;       // DDIM/4 = 32
        const int ij = idx >> 5;       // i*22 + j
        const int i  = ij / JDIM;
        const int j  = ij - i * JDIM;
        const float4 yj = y4[j * 32 + e4];
        const float4 yi = y4[i * 32 + e4];
        const float4 bb = b4[e4];
        float4 o;
        o.x = yj.x - yi.x + bb.x;
        o.y = yj.y - yi.y + bb.y;
        o.z = yj.z - yi.z + bb.z;
        o.w = yj.w - yi.w + bb.w;
        __stcs(outb4 + ij * 32 + e4, o);
    }
}

extern "C" void kernel_launch(void* const* d_in, const int* in_sizes, int n_in,
                              void* d_out, int out_size)
{
    const float* src  = (const float*)d_in[0];   // [B, 22, 128]
    const float* W    = (const float*)d_in[1];   // [128, 128]
    const float* bias = (const float*)d_in[2];   // [128]
    float* out = (float*)d_out;                  // [B, 22, 22, 128]

    const int B = in_sizes[0] / (JDIM * DDIM);   // 2048
    spatial_edge_fused<<<B, NTHREADS>>>(src, W, bias, out);
}

// round 14
// speedup vs baseline: 1.0303x; 1.0303x over previous
#include <cuda_runtime.h>
#include <cstddef>

// out[b,i,j,e] = sum_d (src[b,j,d]-src[b,i,d])*W[e,d] + bias[e]
//             = Y[b,j,e] - Y[b,i,e] + bias[e],  Y = src @ W^T
//
// One block per batch b. Phase 1: GEMM Y[b] (22x128) into SMEM.
// Phase 2: expansion with 1 LDS.128 + 1 STG.128 per output float4:
//   thread owns (i, e4); r = bias - Y[i]; loop j: out = Y[j] + r.

#define JDIM 22
#define DDIM 128
#define KCHUNK 32
#define WPAD 33            // odd stride -> conflict-free column reads
#define NTHREADS 256

__global__ __launch_bounds__(NTHREADS, 4)
void spatial_edge_fused(const float* __restrict__ src,
                        const float* __restrict__ W,
                        const float* __restrict__ bias,
                        float* __restrict__ out)
{
    __shared__ alignas(16) float s_src[JDIM * DDIM];   // 2816 floats
    __shared__ alignas(16) float s_b[DDIM];
    // W chunk during GEMM (128*33 = 4224 floats); first 2816 reused as Y after.
    __shared__ alignas(16) float s_WY[DDIM * WPAD];

    const int b   = blockIdx.x;
    const int tid = threadIdx.x;
    const int tx  = tid & 31;   // lane
    const int ty  = tid >> 5;   // warp 0..7

    const float* srcb = src + (size_t)b * (JDIM * DDIM);

    // ---- load src[b] and bias ----
    for (int i = tid; i < JDIM * DDIM; i += NTHREADS) s_src[i] = srcb[i];
    if (tid < DDIM) s_b[tid] = __ldg(&bias[tid]);

    // Prefetch W chunk 0 into registers (16 elems/thread, strided)
    float wreg[16];
    #pragma unroll
    for (int q = 0; q < 16; q++) {
        const int i  = tid + q * NTHREADS;      // 0..4095
        const int e  = i >> 5;
        const int dd = i & 31;
        wreg[q] = __ldg(&W[e * DDIM + dd]);
    }

    // Thread computes rows {ty, ty+8, ty+16} x cols {tx, tx+32, tx+64, tx+96}
    const int row0 = ty;
    const int row1 = ty + 8;
    const bool has2 = (ty < 6);
    const int row2 = has2 ? (ty + 16) : ty;   // clamp

    float acc[3][4];
    #pragma unroll
    for (int r = 0; r < 3; r++)
        #pragma unroll
        for (int k = 0; k < 4; k++) acc[r][k] = 0.0f;

    // ---- GEMM: Y = src @ W^T, K in chunks of 32, W double-staged via regs ----
    #pragma unroll 1
    for (int c = 0; c < DDIM / KCHUNK; c++) {
        __syncthreads();   // prior chunk's reads done (covers src/bias on c=0)
        #pragma unroll
        for (int q = 0; q < 16; q++) {
            const int i  = tid + q * NTHREADS;
            const int e  = i >> 5;
            const int dd = i & 31;
            s_WY[e * WPAD + dd] = wreg[q];
        }
        __syncthreads();

        if (c + 1 < DDIM / KCHUNK) {
            const int d0n = (c + 1) * KCHUNK;
            #pragma unroll
            for (int q = 0; q < 16; q++) {
                const int i  = tid + q * NTHREADS;
                const int e  = i >> 5;
                const int dd = i & 31;
                wreg[q] = __ldg(&W[e * DDIM + d0n + dd]);
            }
        }

        const int d0 = c * KCHUNK;
        #pragma unroll 4
        for (int dd = 0; dd < KCHUNK; dd++) {
            const float w0 = s_WY[(tx      ) * WPAD + dd];
            const float w1 = s_WY[(tx + 32 ) * WPAD + dd];
            const float w2 = s_WY[(tx + 64 ) * WPAD + dd];
            const float w3 = s_WY[(tx + 96 ) * WPAD + dd];
            const int d = d0 + dd;
            const float s0 = s_src[row0 * DDIM + d];   // warp broadcast
            const float s1 = s_src[row1 * DDIM + d];
            const float s2 = s_src[row2 * DDIM + d];
            acc[0][0] += s0 * w0; acc[0][1] += s0 * w1;
            acc[0][2] += s0 * w2; acc[0][3] += s0 * w3;
            acc[1][0] += s1 * w0; acc[1][1] += s1 * w1;
            acc[1][2] += s1 * w2; acc[1][3] += s1 * w3;
            acc[2][0] += s2 * w0; acc[2][1] += s2 * w1;
            acc[2][2] += s2 * w2; acc[2][3] += s2 * w3;
        }
    }

    // ---- write Y into s_WY[0:2816] (all W reads finished) ----
    __syncthreads();
    float* s_Y = s_WY;
    #pragma unroll
    for (int k = 0; k < 4; k++) {
        s_Y[row0 * DDIM + tx + 32 * k] = acc[0][k];
        s_Y[row1 * DDIM + tx + 32 * k] = acc[1][k];
    }
    if (has2) {
        #pragma unroll
        for (int k = 0; k < 4; k++)
            s_Y[row2 * DDIM + tx + 32 * k] = acc[2][k];
    }
    __syncthreads();

    // ---- expansion: thread owns (i, e4); out[b,i,j,:] = Y[j] + (bias - Y[i]) ----
    const float4* y4 = reinterpret_cast<const float4*>(s_Y);
    const float4* b4 = reinterpret_cast<const float4*>(s_b);
    float4* outb4 = reinterpret_cast<float4*>(out + (size_t)b * (JDIM * JDIM * DDIM));

    const int npairs = JDIM * (DDIM / 4);   // 22 * 32 = 704
    #pragma unroll 1
    for (int pair = tid; pair < npairs; pair += NTHREADS) {
        const int i  = pair >> 5;       // 0..21  (constant per warp)
        const int e4 = pair & 31;       // = lane -> coalesced stores
        const float4 yi = y4[i * 32 + e4];
        const float4 bb = b4[e4];
        float4 r;
        r.x = bb.x - yi.x; r.y = bb.y - yi.y;
        r.z = bb.z - yi.z; r.w = bb.w - yi.w;

        float4* orow = outb4 + (size_t)i * (JDIM * 32) + e4;
        #pragma unroll
        for (int j = 0; j < JDIM; j++) {
            const float4 yj = y4[j * 32 + e4];
            float4 o;
            o.x = yj.x + r.x; o.y = yj.y + r.y;
            o.z = yj.z + r.z; o.w = yj.w + r.w;
            __stcs(orow + j * 32, o);
        }
    }
}

extern "C" void kernel_launch(void* const* d_in, const int* in_sizes, int n_in,
                              void* d_out, int out_size)
{
    const float* src  = (const float*)d_in[0];   // [B, 22, 128]
    const float* W    = (const float*)d_in[1];   // [128, 128]
    const float* bias = (const float*)d_in[2];   // [128]
    float* out = (float*)d_out;                  // [B, 22, 22, 128]

    const int B = in_sizes[0] / (JDIM * DDIM);   // 2048
    spatial_edge_fused<<<B, NTHREADS>>>(src, W, bias, out);
}